// round 1
// baseline (speedup 1.0000x reference)
#include <cuda_runtime.h>
#include <math.h>

// ---------------------------------------------------------------------------
// Problem constants (shapes are fixed by the dataset; runtime values derived
// from in_sizes where it matters).
// ---------------------------------------------------------------------------
#define TM 128          // tokens per CTA tile
#define THREADS 256
#define D_IN 64
#define H1N 128
#define H2N 64
#define H3N 16

// pitches (floats) for shared activation tiles
#define H1P 132
#define H2P 68
#define H3P 17

// shared layout offsets (in floats)
#define OFF_W1 0                       // 64*128 = 8192
#define OFF_W2 (OFF_W1 + 8192)         // 128*64 = 8192
#define OFF_W3 (OFF_W2 + 8192)         // 64*16  = 1024
#define OFF_B1 (OFF_W3 + 1024)         // 128
#define OFF_B2 (OFF_B1 + 128)          // 64
#define OFF_B3 (OFF_B2 + 64)           // 16
#define OFF_W4 (OFF_B3 + 16)           // 16
#define OFF_B4 (OFF_W4 + 16)           // 1 (+3 pad)
#define OFF_X  (OFF_B4 + 4)            // 128*64 = 8192
#define OFF_H1 (OFF_X + 8192)          // 128*132 = 16896
#define OFF_H2 (OFF_H1 + 128*H1P)      // 128*68 = 8704
#define OFF_H3 (OFF_H2 + 128*H2P)      // 128*17 = 2176
#define SMEM_FLOATS (OFF_H3 + 128*H3P)
#define SMEM_BYTES (SMEM_FLOATS * 4)   // 214,416 B < 227 KB

// scratch logits
__device__ float g_logits[1 << 20];

// ---------------------------------------------------------------------------
// f32x2 packed-FMA helpers (sm_103a; ptxas never emits FFMA2 from C++)
// ---------------------------------------------------------------------------
typedef unsigned long long ull;

__device__ __forceinline__ ull pk(float lo, float hi) {
    ull r;
    asm("mov.b64 %0, {%1, %2};" : "=l"(r) : "f"(lo), "f"(hi));
    return r;
}
__device__ __forceinline__ void unpk(ull v, float& lo, float& hi) {
    asm("mov.b64 {%0, %1}, %2;" : "=f"(lo), "=f"(hi) : "l"(v));
}
__device__ __forceinline__ ull fma2(ull a, ull b, ull c) {
    ull d;
    asm("fma.rn.f32x2 %0, %1, %2, %3;" : "=l"(d) : "l"(a), "l"(b), "l"(c));
    return d;
}

// accurate-enough fast tanh: 2 MUFU + a few FMAs, err ~1e-6
__device__ __forceinline__ float tanh_fast(float x) {
    float e = __expf(2.0f * x);            // MUFU.EX2 path
    return 1.0f - __fdividef(2.0f, e + 1.0f);  // MUFU.RCP path
}

// ---------------------------------------------------------------------------
// Fused 4-layer MLP -> logits. One CTA = 128 tokens.
// ---------------------------------------------------------------------------
__global__ void __launch_bounds__(THREADS, 1)
mlp_kernel(const float* __restrict__ x,
           const float* __restrict__ W1, const float* __restrict__ b1,
           const float* __restrict__ W2, const float* __restrict__ b2,
           const float* __restrict__ W3, const float* __restrict__ b3,
           const float* __restrict__ W4, const float* __restrict__ b4) {
    extern __shared__ float sm[];
    float* sW1 = sm + OFF_W1;
    float* sW2 = sm + OFF_W2;
    float* sW3 = sm + OFF_W3;
    float* sB1 = sm + OFF_B1;
    float* sB2 = sm + OFF_B2;
    float* sB3 = sm + OFF_B3;
    float* sW4 = sm + OFF_W4;
    float* sB4 = sm + OFF_B4;
    float* sX  = sm + OFF_X;
    float* sH1 = sm + OFF_H1;
    float* sH2 = sm + OFF_H2;
    float* sH3 = sm + OFF_H3;

    const int tid = threadIdx.x;
    const long long base = (long long)blockIdx.x * TM;

    // ---- stage weights (coalesced float4) ----
    {
        const float4* gW1 = (const float4*)W1;
        const float4* gW2 = (const float4*)W2;
        const float4* gW3 = (const float4*)W3;
        float4* dW1 = (float4*)sW1;
        float4* dW2 = (float4*)sW2;
        float4* dW3 = (float4*)sW3;
#pragma unroll
        for (int i = 0; i < 8; i++) dW1[tid + i * THREADS] = gW1[tid + i * THREADS];
#pragma unroll
        for (int i = 0; i < 8; i++) dW2[tid + i * THREADS] = gW2[tid + i * THREADS];
        dW3[tid] = gW3[tid];  // 256 float4 = 1024 floats
        if (tid < 128) sB1[tid] = b1[tid];
        if (tid < 64)  sB2[tid] = b2[tid];
        if (tid < 16)  { sB3[tid] = b3[tid]; sW4[tid] = W4[tid]; }
        if (tid == 0)  sB4[0] = b4[0];
    }

    // ---- stage X tile row-major [m][64] (coalesced float4) ----
    {
        const float4* gx = (const float4*)(x + base * D_IN);
        const int c = tid & 15;          // float4 column within token row
        const int t0 = tid >> 4;         // 16 tokens per iteration
#pragma unroll
        for (int it = 0; it < 8; it++) {
            int t = t0 + it * 16;
            float4 v = gx[t * 16 + c];
            *(float4*)&sX[t * D_IN + c * 4] = v;
        }
    }
    __syncthreads();

    const int ty = tid >> 4;   // 0..15
    const int tx = tid & 15;   // 0..15

    // ======================= Layer 1: 128x128 = 128x64 @ 64x128 ============
    {
        const int m0 = ty * 8, n0 = tx * 8;
        ull acc[8][4];
        {
            float4 bA = *(const float4*)&sB1[n0];
            float4 bB = *(const float4*)&sB1[n0 + 4];
            ull p0 = pk(bA.x, bA.y), p1 = pk(bA.z, bA.w);
            ull p2 = pk(bB.x, bB.y), p3 = pk(bB.z, bB.w);
#pragma unroll
            for (int i = 0; i < 8; i++) { acc[i][0] = p0; acc[i][1] = p1; acc[i][2] = p2; acc[i][3] = p3; }
        }
#pragma unroll 4
        for (int k = 0; k < D_IN; k++) {
            float4 wA = *(const float4*)&sW1[k * H1N + n0];
            float4 wB = *(const float4*)&sW1[k * H1N + n0 + 4];
            ull wp0 = pk(wA.x, wA.y), wp1 = pk(wA.z, wA.w);
            ull wp2 = pk(wB.x, wB.y), wp3 = pk(wB.z, wB.w);
#pragma unroll
            for (int i = 0; i < 8; i++) {
                float xv = sX[(m0 + i) * D_IN + k];
                ull xx = pk(xv, xv);
                acc[i][0] = fma2(xx, wp0, acc[i][0]);
                acc[i][1] = fma2(xx, wp1, acc[i][1]);
                acc[i][2] = fma2(xx, wp2, acc[i][2]);
                acc[i][3] = fma2(xx, wp3, acc[i][3]);
            }
        }
#pragma unroll
        for (int i = 0; i < 8; i++) {
#pragma unroll
            for (int j = 0; j < 4; j++) {
                float lo, hi; unpk(acc[i][j], lo, hi);
                float2 o = make_float2(tanh_fast(lo), tanh_fast(hi));
                *(float2*)&sH1[(m0 + i) * H1P + n0 + 2 * j] = o;
            }
        }
    }
    __syncthreads();

    // ======================= Layer 2: 128x64 = 128x128 @ 128x64 ============
    {
        const int m0 = ty * 8, n0 = tx * 4;
        ull acc[8][2];
        {
            float4 bA = *(const float4*)&sB2[n0];
            ull p0 = pk(bA.x, bA.y), p1 = pk(bA.z, bA.w);
#pragma unroll
            for (int i = 0; i < 8; i++) { acc[i][0] = p0; acc[i][1] = p1; }
        }
#pragma unroll 4
        for (int k = 0; k < H1N; k++) {
            float4 w = *(const float4*)&sW2[k * H2N + n0];
            ull wp0 = pk(w.x, w.y), wp1 = pk(w.z, w.w);
#pragma unroll
            for (int i = 0; i < 8; i++) {
                float xv = sH1[(m0 + i) * H1P + k];
                ull xx = pk(xv, xv);
                acc[i][0] = fma2(xx, wp0, acc[i][0]);
                acc[i][1] = fma2(xx, wp1, acc[i][1]);
            }
        }
#pragma unroll
        for (int i = 0; i < 8; i++) {
#pragma unroll
            for (int j = 0; j < 2; j++) {
                float lo, hi; unpk(acc[i][j], lo, hi);
                float2 o = make_float2(tanh_fast(lo), tanh_fast(hi));
                *(float2*)&sH2[(m0 + i) * H2P + n0 + 2 * j] = o;
            }
        }
    }
    __syncthreads();

    // ======================= Layer 3: 128x16 = 128x64 @ 64x16 ==============
    {
        const int m0 = ty * 8;    // 8 tokens
        const int n = tx;         // 1 neuron
        ull acc[4];
        {
            float bv = sB3[n];
            ull p = pk(bv, bv);
#pragma unroll
            for (int p4 = 0; p4 < 4; p4++) acc[p4] = p;
        }
#pragma unroll 4
        for (int k = 0; k < H2N; k++) {
            float wv = sW3[k * H3N + n];
            ull ww = pk(wv, wv);
#pragma unroll
            for (int p4 = 0; p4 < 4; p4++) {
                float x0 = sH2[(m0 + 2 * p4) * H2P + k];
                float x1 = sH2[(m0 + 2 * p4 + 1) * H2P + k];
                acc[p4] = fma2(pk(x0, x1), ww, acc[p4]);
            }
        }
#pragma unroll
        for (int p4 = 0; p4 < 4; p4++) {
            float lo, hi; unpk(acc[p4], lo, hi);
            sH3[(m0 + 2 * p4) * H3P + n]     = tanh_fast(lo);
            sH3[(m0 + 2 * p4 + 1) * H3P + n] = tanh_fast(hi);
        }
    }
    __syncthreads();

    // ======================= Layer 4: 128x1 = 128x16 @ 16x1 ================
    if (tid < TM) {
        float a = sB4[0];
#pragma unroll
        for (int k = 0; k < H3N; k++) a = fmaf(sH3[tid * H3P + k], sW4[k], a);
        g_logits[base + tid] = a;
    }
}

// ---------------------------------------------------------------------------
// Per-segment softmax. Global-max subtraction cancels mathematically, so we
// use the per-segment max (identical result, better numerics, no global pass).
// One CTA per segment.
// ---------------------------------------------------------------------------
#define SOFT_THREADS 512

__device__ __forceinline__ float warpRedMax(float v) {
#pragma unroll
    for (int o = 16; o > 0; o >>= 1) v = fmaxf(v, __shfl_xor_sync(0xffffffffu, v, o));
    return v;
}
__device__ __forceinline__ float warpRedSum(float v) {
#pragma unroll
    for (int o = 16; o > 0; o >>= 1) v += __shfl_xor_sync(0xffffffffu, v, o);
    return v;
}
__device__ __forceinline__ int warpRedSumI(int v) {
#pragma unroll
    for (int o = 16; o > 0; o >>= 1) v += __shfl_xor_sync(0xffffffffu, v, o);
    return v;
}

__global__ void __launch_bounds__(SOFT_THREADS)
softmax_seg_kernel(const int* __restrict__ sizes, float* __restrict__ out) {
    __shared__ float shf[16];
    __shared__ int shi[16];
    __shared__ float bcastf;
    __shared__ int bcasti;

    const int b = blockIdx.x;
    const int tid = threadIdx.x;
    const int wid = tid >> 5, lid = tid & 31;
    const int nwarp = SOFT_THREADS / 32;

    // segment offset = prefix sum of sizes[0..b)
    int part = 0;
    for (int i = tid; i < b; i += SOFT_THREADS) part += sizes[i];
    part = warpRedSumI(part);
    if (lid == 0) shi[wid] = part;
    __syncthreads();
    if (wid == 0) {
        int v = (lid < nwarp) ? shi[lid] : 0;
        v = warpRedSumI(v);
        if (lid == 0) bcasti = v;
    }
    __syncthreads();
    const int off = bcasti;
    const int len = sizes[b];

    // max
    float mx = -3.402823466e38f;
    for (int i = tid; i < len; i += SOFT_THREADS) mx = fmaxf(mx, g_logits[off + i]);
    mx = warpRedMax(mx);
    if (lid == 0) shf[wid] = mx;
    __syncthreads();
    if (wid == 0) {
        float v = (lid < nwarp) ? shf[lid] : -3.402823466e38f;
        v = warpRedMax(v);
        if (lid == 0) bcastf = v;
    }
    __syncthreads();
    mx = bcastf;

    // exp + sum
    float s = 0.0f;
    for (int i = tid; i < len; i += SOFT_THREADS) {
        float e = __expf(g_logits[off + i] - mx);
        out[off + i] = e;
        s += e;
    }
    s = warpRedSum(s);
    __syncthreads();   // shf reuse
    if (lid == 0) shf[wid] = s;
    __syncthreads();
    if (wid == 0) {
        float v = (lid < nwarp) ? shf[lid] : 0.0f;
        v = warpRedSum(v);
        if (lid == 0) bcastf = v;
    }
    __syncthreads();
    const float inv = 1.0f / bcastf;

    for (int i = tid; i < len; i += SOFT_THREADS) out[off + i] *= inv;
}

// If the harness output also carries the passthrough `sizes` (tuple output),
// emit them as float values after the softmax block.
__global__ void tail_sizes_kernel(const int* __restrict__ sizes, float* __restrict__ out,
                                  int n, int basepos) {
    int i = blockIdx.x * blockDim.x + threadIdx.x;
    if (i < n) out[basepos + i] = (float)sizes[i];
}

// ---------------------------------------------------------------------------
extern "C" void kernel_launch(void* const* d_in, const int* in_sizes, int n_in,
                              void* d_out, int out_size) {
    const float* x   = (const float*)d_in[0];
    const int* sizes = (const int*)d_in[1];
    const float* W1  = (const float*)d_in[2];
    const float* b1  = (const float*)d_in[3];
    const float* W2  = (const float*)d_in[4];
    const float* b2  = (const float*)d_in[5];
    const float* W3  = (const float*)d_in[6];
    const float* b3  = (const float*)d_in[7];
    const float* W4  = (const float*)d_in[8];
    const float* b4  = (const float*)d_in[9];
    float* out = (float*)d_out;

    const int total = in_sizes[0] / D_IN;   // number of tokens
    const int B     = in_sizes[1];          // number of segments

    cudaFuncSetAttribute(mlp_kernel, cudaFuncAttributeMaxDynamicSharedMemorySize, SMEM_BYTES);

    mlp_kernel<<<total / TM, THREADS, SMEM_BYTES>>>(x, W1, b1, W2, b2, W3, b3, W4, b4);
    softmax_seg_kernel<<<B, SOFT_THREADS>>>(sizes, out);

    if (out_size > total) {
        int n = out_size - total;
        tail_sizes_kernel<<<(n + 255) / 256, 256>>>(sizes, out, n, total);
    }
}